// round 3
// baseline (speedup 1.0000x reference)
#include <cuda_runtime.h>

#define NB      65536
#define QF      12
#define NP      78
#define THREADS 128
#define SPB     32      // samples per block (4 threads per sample)

// ---- shared memory layout (float offsets) ----
#define OFF_WA   0        // [10][32]   sW1 rows 0..9, padded cols 30,31 = 0
#define OFF_WBT  320      // [30][12]   sW1 rows 10..19 transposed, pad d=10,11 = 0
#define OFF_C1   680      // [78][30]   tok_p@sW1[20:30] + sb1
#define OFF_W2   3020     // [30][20]
#define OFF_W3   3620     // [20]
#define OFF_SB2  3640     // [20]
#define OFF_CW1  3660     // [6][20]
#define OFF_CB1  3780     // [6][20]
#define OFF_CW2  3900     // [6][20][12]
#define OFF_CB2  5340     // [6][12]
#define OFF_OUTW 5412     // [80]
#define OFF_MISC 5492     // [0]=sb3, [1]=out_b
#define OFF_PETA 5496     // [128]
#define OFF_E    5624     // [SPB][148]; rows of 12 floats per feature
#define E_STRIDE 148
#define SMEM_FLOATS (OFF_E + SPB * E_STRIDE)

extern __shared__ float smem[];

__global__ void __launch_bounds__(THREADS, 5)
pin_kernel(const float* __restrict__ x_cont, const int* __restrict__ x_cat,
           const float* __restrict__ exposure,
           const float* __restrict__ cont_W1, const float* __restrict__ cont_b1,
           const float* __restrict__ cont_W2, const float* __restrict__ cont_b2,
           const float* __restrict__ cat_tables, const float* __restrict__ tokens,
           const float* __restrict__ sW1, const float* __restrict__ sb1,
           const float* __restrict__ sW2, const float* __restrict__ sb2,
           const float* __restrict__ sW3, const float* __restrict__ sb3,
           const float* __restrict__ out_w, const float* __restrict__ out_b,
           float* __restrict__ out)
{
    const int tid  = threadIdx.x;
    const int lane = tid & 31;   // sample within block
    const int sub  = tid >> 5;   // quarter of the pair work

    // ---------------- cooperative weight staging ----------------
    for (int i = tid; i < 320; i += THREADS) {          // WA padded
        int d = i >> 5, l = i & 31;
        smem[OFF_WA + i] = (l < 30) ? sW1[d * 30 + l] : 0.f;
    }
    for (int i = tid; i < 360; i += THREADS) {          // WB transposed
        int l = i / 12, d = i % 12;
        smem[OFF_WBT + i] = (d < 10) ? sW1[(10 + d) * 30 + l] : 0.f;
    }
    for (int i = tid; i < 600; i += THREADS) smem[OFF_W2 + i] = sW2[i];
    for (int i = tid; i < 20; i += THREADS) {
        smem[OFF_W3 + i]  = sW3[i];
        smem[OFF_SB2 + i] = sb2[i];
    }
    for (int i = tid; i < 120; i += THREADS) {
        smem[OFF_CW1 + i] = cont_W1[i];
        smem[OFF_CB1 + i] = cont_b1[i];
    }
    for (int i = tid; i < 1200; i += THREADS) {
        int c = i / 200, r = i % 200, h = r / 10, d = r % 10;
        smem[OFF_CW2 + (c * 20 + h) * 12 + d] = cont_W2[i];
    }
    for (int i = tid; i < 60; i += THREADS)
        smem[OFF_CB2 + (i / 10) * 12 + (i % 10)] = cont_b2[i];
    for (int i = tid; i < NP; i += THREADS) smem[OFF_OUTW + i] = out_w[i];
    if (tid == 0) { smem[OFF_MISC + 0] = sb3[0]; smem[OFF_MISC + 1] = out_b[0]; }
    for (int i = tid; i < NP * 30; i += THREADS) {      // per-pair token bias
        int p = i / 30, l = i % 30;
        float acc = sb1[l];
#pragma unroll
        for (int d = 0; d < 10; ++d)
            acc = fmaf(tokens[p * 10 + d], sW1[(20 + d) * 30 + l], acc);
        smem[OFF_C1 + i] = acc;
    }
    __syncthreads();

    // ---------------- feature net (split across subs) ----------------
    const int b = blockIdx.x * SPB + lane;
    float* myE = smem + OFF_E + lane * E_STRIDE;

    if (sub < 2) {
        // continuous features: sub0 -> c 0..2, sub1 -> c 3..5
#pragma unroll 1
        for (int ci = 0; ci < 3; ++ci) {
            int c = sub * 3 + ci;
            float x = x_cont[b * 6 + c];
            float acc[10];
#pragma unroll
            for (int d = 0; d < 10; ++d) acc[d] = smem[OFF_CB2 + c * 12 + d];
#pragma unroll
            for (int h = 0; h < 20; ++h) {
                float hv = fmaxf(fmaf(x, smem[OFF_CW1 + c * 20 + h],
                                      smem[OFF_CB1 + c * 20 + h]), 0.f);
#pragma unroll
                for (int d = 0; d < 10; ++d)
                    acc[d] = fmaf(hv, smem[OFF_CW2 + (c * 20 + h) * 12 + d], acc[d]);
            }
#pragma unroll
            for (int d = 0; d < 10; ++d) myE[c * 12 + d] = acc[d];
        }
    } else {
        // categorical embeddings: sub2 -> c 0..2, sub3 -> c 3..5
#pragma unroll 1
        for (int ci = 0; ci < 3; ++ci) {
            int c = (sub - 2) * 3 + ci;
            int idx = x_cat[b * 6 + c];
            const float* row = cat_tables + (size_t)(c * 100 + idx) * 10;
#pragma unroll
            for (int d = 0; d < 10; ++d) myE[(6 + c) * 12 + d] = row[d];
        }
    }
    __syncthreads();

    // ---------------- pair loop ----------------
    // rows per sub (balanced 19/18/20/21 pairs), packed nibbles low->high
    const unsigned pk = (sub == 0) ? 0xA70u : (sub == 1) ? 0xB61u
                       : (sub == 2) ? 0x952u : 0x843u;
    const float raw_bias = smem[OFF_MISC + 0];
    float eta = 0.f;

    // hoist W3 (loop-invariant) into registers
    float w3[20];
    {
        const float4* w3r = (const float4*)(smem + OFF_W3);
#pragma unroll
        for (int v = 0; v < 5; ++v) {
            float4 w = w3r[v];
            w3[v*4+0]=w.x; w3[v*4+1]=w.y; w3[v*4+2]=w.z; w3[v*4+3]=w.w;
        }
    }

#pragma unroll 1
    for (int i3 = 0; i3 < 3; ++i3) {
        const int j = (pk >> (4 * i3)) & 15;

        float4 e0 = *(const float4*)(myE + j * 12);
        float4 e1 = *(const float4*)(myE + j * 12 + 4);
        float4 e2 = *(const float4*)(myE + j * 12 + 8);
        float ej[10] = {e0.x,e0.y,e0.z,e0.w,e1.x,e1.y,e1.z,e1.w,e2.x,e2.y};

        float A[32];
#pragma unroll
        for (int l = 0; l < 32; ++l) A[l] = 0.f;
#pragma unroll
        for (int d = 0; d < 10; ++d) {
            const float4* wr = (const float4*)(smem + OFF_WA + d * 32);
#pragma unroll
            for (int v = 0; v < 8; ++v) {
                float4 w = wr[v];
                A[v*4+0] = fmaf(ej[d], w.x, A[v*4+0]);
                A[v*4+1] = fmaf(ej[d], w.y, A[v*4+1]);
                A[v*4+2] = fmaf(ej[d], w.z, A[v*4+2]);
                A[v*4+3] = fmaf(ej[d], w.w, A[v*4+3]);
            }
        }

        int p = (j * (25 - j)) >> 1;   // pairs before row j

#pragma unroll 1
        for (int k = j; k < QF; ++k, ++p) {
            float4 k0 = *(const float4*)(myE + k * 12);
            float4 k1 = *(const float4*)(myE + k * 12 + 4);
            float4 k2 = *(const float4*)(myE + k * 12 + 8);
            float ek[10] = {k0.x,k0.y,k0.z,k0.w,k1.x,k1.y,k1.z,k1.w,k2.x,k2.y};

            float h2[20];
            {
                const float4* sb = (const float4*)(smem + OFF_SB2);
#pragma unroll
                for (int v = 0; v < 5; ++v) {
                    float4 s = sb[v];
                    h2[v*4+0]=s.x; h2[v*4+1]=s.y; h2[v*4+2]=s.z; h2[v*4+3]=s.w;
                }
            }
            const float* c1p = smem + OFF_C1 + p * 30;

#pragma unroll
            for (int l = 0; l < 30; ++l) {
                const float4* wb = (const float4*)(smem + OFF_WBT + l * 12);
                float4 w0 = wb[0], w1 = wb[1], w2v = wb[2];
                float s0 = fmaf(ek[0], w0.x, A[l]);
                s0 = fmaf(ek[1], w0.y, s0);
                s0 = fmaf(ek[2], w0.z, s0);
                s0 = fmaf(ek[3], w0.w, s0);
                s0 = fmaf(ek[4], w1.x, s0);
                float s1 = fmaf(ek[5], w1.y, c1p[l]);
                s1 = fmaf(ek[6], w1.z, s1);
                s1 = fmaf(ek[7], w1.w, s1);
                s1 = fmaf(ek[8], w2v.x, s1);
                s1 = fmaf(ek[9], w2v.y, s1);
                float h1 = fmaxf(s0 + s1, 0.f);

                const float4* w2r = (const float4*)(smem + OFF_W2 + l * 20);
                float4 a0 = w2r[0], a1 = w2r[1], a2 = w2r[2], a3 = w2r[3], a4 = w2r[4];
                h2[0]  = fmaf(h1, a0.x, h2[0]);  h2[1]  = fmaf(h1, a0.y, h2[1]);
                h2[2]  = fmaf(h1, a0.z, h2[2]);  h2[3]  = fmaf(h1, a0.w, h2[3]);
                h2[4]  = fmaf(h1, a1.x, h2[4]);  h2[5]  = fmaf(h1, a1.y, h2[5]);
                h2[6]  = fmaf(h1, a1.z, h2[6]);  h2[7]  = fmaf(h1, a1.w, h2[7]);
                h2[8]  = fmaf(h1, a2.x, h2[8]);  h2[9]  = fmaf(h1, a2.y, h2[9]);
                h2[10] = fmaf(h1, a2.z, h2[10]); h2[11] = fmaf(h1, a2.w, h2[11]);
                h2[12] = fmaf(h1, a3.x, h2[12]); h2[13] = fmaf(h1, a3.y, h2[13]);
                h2[14] = fmaf(h1, a3.z, h2[14]); h2[15] = fmaf(h1, a3.w, h2[15]);
                h2[16] = fmaf(h1, a4.x, h2[16]); h2[17] = fmaf(h1, a4.y, h2[17]);
                h2[18] = fmaf(h1, a4.z, h2[18]); h2[19] = fmaf(h1, a4.w, h2[19]);
            }

            float raw = raw_bias;
#pragma unroll
            for (int o = 0; o < 20; ++o)
                raw = fmaf(fmaxf(h2[o], 0.f), w3[o], raw);

            float ht = fminf(fmaxf(raw * (1.f/6.f) + 0.5f, 0.f), 1.f) - 0.5f;
            eta = fmaf(smem[OFF_OUTW + p], ht, eta);
        }
    }

    smem[OFF_PETA + tid] = eta;
    __syncthreads();
    if (tid < 32) {
        float e = smem[OFF_PETA + tid]      + smem[OFF_PETA + tid + 32]
                + smem[OFF_PETA + tid + 64] + smem[OFF_PETA + tid + 96];
        e += smem[OFF_MISC + 1];
        e = fminf(fmaxf(e, -20.f), 20.f);
        out[b] = __expf(e) * exposure[b];
    }
}

extern "C" void kernel_launch(void* const* d_in, const int* in_sizes, int n_in,
                              void* d_out, int out_size)
{
    (void)in_sizes; (void)n_in; (void)out_size;
    size_t shmem = SMEM_FLOATS * sizeof(float);
    cudaFuncSetAttribute(pin_kernel, cudaFuncAttributeMaxDynamicSharedMemorySize,
                         (int)shmem);
    pin_kernel<<<NB / SPB, THREADS, shmem>>>(
        (const float*)d_in[0],  (const int*)d_in[1],   (const float*)d_in[2],
        (const float*)d_in[3],  (const float*)d_in[4], (const float*)d_in[5],
        (const float*)d_in[6],  (const float*)d_in[7], (const float*)d_in[8],
        (const float*)d_in[9],  (const float*)d_in[10],(const float*)d_in[11],
        (const float*)d_in[12], (const float*)d_in[13],(const float*)d_in[14],
        (const float*)d_in[15], (const float*)d_in[16],
        (float*)d_out);
}

// round 4
// speedup vs baseline: 1.1368x; 1.1368x over previous
#include <cuda_runtime.h>

#define NB      65536
#define QF      12
#define NP      78
#define THREADS 128
#define SPB     32      // samples per block (4 threads per sample)

// ---- shared memory layout (float offsets) ----
#define OFF_WA   0        // [10][32]   sW1 rows 0..9, cols padded to 32 (0-fill)
#define OFF_WBT  320      // [30][12]   sW1 rows 10..19 transposed, pad d=10,11
#define OFF_C1   680      // [78][30]   tok_p@sW1[20:30] + sb1
#define OFF_W2T  3020     // [20][32]   sW2 transposed (o-major), pad l=30,31
#define OFF_W3   3660     // [20]
#define OFF_SB2  3680     // [20]
#define OFF_CW1  3700     // [6][20]
#define OFF_CB1  3820     // [6][20]
#define OFF_CW2  3940     // [6][20][12]
#define OFF_CB2  5380     // [6][12]
#define OFF_OUTW 5452     // [80]
#define OFF_MISC 5532     // [0]=sb3, [1]=out_b
#define OFF_PETA 5536     // [128]
#define OFF_E    5664     // [SPB][148]
#define E_STRIDE 148
#define SMEM_FLOATS (OFF_E + SPB * E_STRIDE)

extern __shared__ float smem[];

__global__ void __launch_bounds__(THREADS, 4)
pin_kernel(const float* __restrict__ x_cont, const int* __restrict__ x_cat,
           const float* __restrict__ exposure,
           const float* __restrict__ cont_W1, const float* __restrict__ cont_b1,
           const float* __restrict__ cont_W2, const float* __restrict__ cont_b2,
           const float* __restrict__ cat_tables, const float* __restrict__ tokens,
           const float* __restrict__ sW1, const float* __restrict__ sb1,
           const float* __restrict__ sW2, const float* __restrict__ sb2,
           const float* __restrict__ sW3, const float* __restrict__ sb3,
           const float* __restrict__ out_w, const float* __restrict__ out_b,
           float* __restrict__ out)
{
    const int tid  = threadIdx.x;
    const int lane = tid & 31;   // sample within block
    const int sub  = tid >> 5;   // quarter of the pair work

    // ---------------- cooperative weight staging ----------------
    for (int i = tid; i < 320; i += THREADS) {          // WA padded
        int d = i >> 5, l = i & 31;
        smem[OFF_WA + i] = (l < 30) ? sW1[d * 30 + l] : 0.f;
    }
    for (int i = tid; i < 360; i += THREADS) {          // WB transposed
        int l = i / 12, d = i % 12;
        smem[OFF_WBT + i] = (d < 10) ? sW1[(10 + d) * 30 + l] : 0.f;
    }
    for (int i = tid; i < 640; i += THREADS) {          // W2 transposed, padded
        int o = i >> 5, l = i & 31;
        smem[OFF_W2T + i] = (l < 30) ? sW2[l * 20 + o] : 0.f;
    }
    for (int i = tid; i < 20; i += THREADS) {
        smem[OFF_W3 + i]  = sW3[i];
        smem[OFF_SB2 + i] = sb2[i];
    }
    for (int i = tid; i < 120; i += THREADS) {
        smem[OFF_CW1 + i] = cont_W1[i];
        smem[OFF_CB1 + i] = cont_b1[i];
    }
    for (int i = tid; i < 1200; i += THREADS) {
        int c = i / 200, r = i % 200, h = r / 10, d = r % 10;
        smem[OFF_CW2 + (c * 20 + h) * 12 + d] = cont_W2[i];
    }
    for (int i = tid; i < 60; i += THREADS)
        smem[OFF_CB2 + (i / 10) * 12 + (i % 10)] = cont_b2[i];
    for (int i = tid; i < NP; i += THREADS) smem[OFF_OUTW + i] = out_w[i];
    if (tid == 0) { smem[OFF_MISC + 0] = sb3[0]; smem[OFF_MISC + 1] = out_b[0]; }
    for (int i = tid; i < NP * 30; i += THREADS) {      // per-pair token bias
        int p = i / 30, l = i % 30;
        float acc = sb1[l];
#pragma unroll
        for (int d = 0; d < 10; ++d)
            acc = fmaf(tokens[p * 10 + d], sW1[(20 + d) * 30 + l], acc);
        smem[OFF_C1 + i] = acc;
    }
    __syncthreads();

    // ---------------- feature net (split across subs) ----------------
    const int b = blockIdx.x * SPB + lane;
    float* myE = smem + OFF_E + lane * E_STRIDE;

    if (sub < 2) {
#pragma unroll 1
        for (int ci = 0; ci < 3; ++ci) {
            int c = sub * 3 + ci;
            float x = x_cont[b * 6 + c];
            float acc[10];
#pragma unroll
            for (int d = 0; d < 10; ++d) acc[d] = smem[OFF_CB2 + c * 12 + d];
#pragma unroll
            for (int h = 0; h < 20; ++h) {
                float hv = fmaxf(fmaf(x, smem[OFF_CW1 + c * 20 + h],
                                      smem[OFF_CB1 + c * 20 + h]), 0.f);
#pragma unroll
                for (int d = 0; d < 10; ++d)
                    acc[d] = fmaf(hv, smem[OFF_CW2 + (c * 20 + h) * 12 + d], acc[d]);
            }
#pragma unroll
            for (int d = 0; d < 10; ++d) myE[c * 12 + d] = acc[d];
        }
    } else {
#pragma unroll 1
        for (int ci = 0; ci < 3; ++ci) {
            int c = (sub - 2) * 3 + ci;
            int idx = x_cat[b * 6 + c];
            const float* row = cat_tables + (size_t)(c * 100 + idx) * 10;
#pragma unroll
            for (int d = 0; d < 10; ++d) myE[(6 + c) * 12 + d] = row[d];
        }
    }
    __syncthreads();

    // ---------------- pair loop ----------------
    const unsigned pk = (sub == 0) ? 0xA70u : (sub == 1) ? 0xB61u
                       : (sub == 2) ? 0x952u : 0x843u;
    const float raw_bias = smem[OFF_MISC + 0];
    float eta = 0.f;

#pragma unroll 1
    for (int i3 = 0; i3 < 3; ++i3) {
        const int j = (pk >> (4 * i3)) & 15;

        float4 e0 = *(const float4*)(myE + j * 12);
        float4 e1 = *(const float4*)(myE + j * 12 + 4);
        float4 e2 = *(const float4*)(myE + j * 12 + 8);
        float ej[10] = {e0.x,e0.y,e0.z,e0.w,e1.x,e1.y,e1.z,e1.w,e2.x,e2.y};

        float A[32];
#pragma unroll
        for (int l = 0; l < 32; ++l) A[l] = 0.f;
#pragma unroll
        for (int d = 0; d < 10; ++d) {
            const float4* wr = (const float4*)(smem + OFF_WA + d * 32);
#pragma unroll
            for (int v = 0; v < 8; ++v) {
                float4 w = wr[v];
                A[v*4+0] = fmaf(ej[d], w.x, A[v*4+0]);
                A[v*4+1] = fmaf(ej[d], w.y, A[v*4+1]);
                A[v*4+2] = fmaf(ej[d], w.z, A[v*4+2]);
                A[v*4+3] = fmaf(ej[d], w.w, A[v*4+3]);
            }
        }

        int p = (j * (25 - j)) >> 1;   // pairs before row j

#pragma unroll 1
        for (int k = j; k < QF; ++k, ++p) {
            // ---- phase 1: h1[30] = relu(A + ek@WB + c1p) ----
            float h1[30];
            {
                float4 k0 = *(const float4*)(myE + k * 12);
                float4 k1 = *(const float4*)(myE + k * 12 + 4);
                float4 k2 = *(const float4*)(myE + k * 12 + 8);
                float ek[10] = {k0.x,k0.y,k0.z,k0.w,k1.x,k1.y,k1.z,k1.w,k2.x,k2.y};
                const float* c1p = smem + OFF_C1 + p * 30;
#pragma unroll
                for (int l = 0; l < 30; ++l) {
                    const float4* wb = (const float4*)(smem + OFF_WBT + l * 12);
                    float4 w0 = wb[0], w1 = wb[1], w2v = wb[2];
                    float s0 = fmaf(ek[0], w0.x, A[l]);
                    s0 = fmaf(ek[1], w0.y, s0);
                    s0 = fmaf(ek[2], w0.z, s0);
                    s0 = fmaf(ek[3], w0.w, s0);
                    s0 = fmaf(ek[4], w1.x, s0);
                    float s1 = fmaf(ek[5], w1.y, c1p[l]);
                    s1 = fmaf(ek[6], w1.z, s1);
                    s1 = fmaf(ek[7], w1.w, s1);
                    s1 = fmaf(ek[8], w2v.x, s1);
                    s1 = fmaf(ek[9], w2v.y, s1);
                    h1[l] = fmaxf(s0 + s1, 0.f);
                }
            }

            // ---- phase 2: raw = sb3 + sum_o relu(sb2[o] + h1@W2T[o]) * w3[o] ----
            float raw = raw_bias;
#pragma unroll
            for (int og = 0; og < 5; ++og) {
                float4 sb = *(const float4*)(smem + OFF_SB2 + og * 4);
                float a0 = sb.x, a1 = sb.y, a2 = sb.z, a3 = sb.w;
                const float4* r0 = (const float4*)(smem + OFF_W2T + (og*4+0) * 32);
                const float4* r1 = (const float4*)(smem + OFF_W2T + (og*4+1) * 32);
                const float4* r2 = (const float4*)(smem + OFF_W2T + (og*4+2) * 32);
                const float4* r3 = (const float4*)(smem + OFF_W2T + (og*4+3) * 32);
#pragma unroll
                for (int v = 0; v < 8; ++v) {
                    float4 w0 = r0[v], w1 = r1[v], w2v = r2[v], w3v = r3[v];
                    float hv0 = (v*4+0 < 30) ? h1[(v*4+0 < 30) ? v*4+0 : 0] : 0.f;
                    float hv1 = (v*4+1 < 30) ? h1[(v*4+1 < 30) ? v*4+1 : 0] : 0.f;
                    float hv2 = (v*4+2 < 30) ? h1[(v*4+2 < 30) ? v*4+2 : 0] : 0.f;
                    float hv3 = (v*4+3 < 30) ? h1[(v*4+3 < 30) ? v*4+3 : 0] : 0.f;
                    a0 = fmaf(hv0, w0.x, a0); a1 = fmaf(hv0, w1.x, a1);
                    a2 = fmaf(hv0, w2v.x, a2); a3 = fmaf(hv0, w3v.x, a3);
                    a0 = fmaf(hv1, w0.y, a0); a1 = fmaf(hv1, w1.y, a1);
                    a2 = fmaf(hv1, w2v.y, a2); a3 = fmaf(hv1, w3v.y, a3);
                    a0 = fmaf(hv2, w0.z, a0); a1 = fmaf(hv2, w1.z, a1);
                    a2 = fmaf(hv2, w2v.z, a2); a3 = fmaf(hv2, w3v.z, a3);
                    a0 = fmaf(hv3, w0.w, a0); a1 = fmaf(hv3, w1.w, a1);
                    a2 = fmaf(hv3, w2v.w, a2); a3 = fmaf(hv3, w3v.w, a3);
                }
                float4 w3f = *(const float4*)(smem + OFF_W3 + og * 4);
                raw = fmaf(fmaxf(a0, 0.f), w3f.x, raw);
                raw = fmaf(fmaxf(a1, 0.f), w3f.y, raw);
                raw = fmaf(fmaxf(a2, 0.f), w3f.z, raw);
                raw = fmaf(fmaxf(a3, 0.f), w3f.w, raw);
            }

            float ht = fminf(fmaxf(raw * (1.f/6.f) + 0.5f, 0.f), 1.f) - 0.5f;
            eta = fmaf(smem[OFF_OUTW + p], ht, eta);
        }
    }

    smem[OFF_PETA + tid] = eta;
    __syncthreads();
    if (tid < 32) {
        float e = smem[OFF_PETA + tid]      + smem[OFF_PETA + tid + 32]
                + smem[OFF_PETA + tid + 64] + smem[OFF_PETA + tid + 96];
        e += smem[OFF_MISC + 1];
        e = fminf(fmaxf(e, -20.f), 20.f);
        out[b] = __expf(e) * exposure[b];
    }
}

extern "C" void kernel_launch(void* const* d_in, const int* in_sizes, int n_in,
                              void* d_out, int out_size)
{
    (void)in_sizes; (void)n_in; (void)out_size;
    size_t shmem = SMEM_FLOATS * sizeof(float);
    cudaFuncSetAttribute(pin_kernel, cudaFuncAttributeMaxDynamicSharedMemorySize,
                         (int)shmem);
    pin_kernel<<<NB / SPB, THREADS, shmem>>>(
        (const float*)d_in[0],  (const int*)d_in[1],   (const float*)d_in[2],
        (const float*)d_in[3],  (const float*)d_in[4], (const float*)d_in[5],
        (const float*)d_in[6],  (const float*)d_in[7], (const float*)d_in[8],
        (const float*)d_in[9],  (const float*)d_in[10],(const float*)d_in[11],
        (const float*)d_in[12], (const float*)d_in[13],(const float*)d_in[14],
        (const float*)d_in[15], (const float*)d_in[16],
        (float*)d_out);
}

// round 5
// speedup vs baseline: 14.1458x; 12.4437x over previous
#include <cuda_runtime.h>
#include <cuda_bf16.h>

#define NB      65536
#define THREADS 192
#define SPB     32

// ---- shared memory layout (uint32/float offsets) ----
#define OFF_WA   0        // [10][32] f32 (sW1 rows 0..9, col-padded)
#define OFF_WB   320      // [10][32] f32 (sW1 rows 10..19)
#define OFF_W2   640      // [32][20] f32 (rows 30,31 zero)
#define OFF_W3   1280     // [20]
#define OFF_SB2  1300     // [20]
#define OFF_CW1  1320     // [6][20]
#define OFF_CB1  1440     // [6][20]
#define OFF_CW2  1560     // [6][20][12]
#define OFF_CB2  3000     // [6][12]
#define OFF_OUTW 3072     // [80]
#define OFF_MISC 3152     // [0]=sb3,[1]=out_b
#define OFF_PETA 3156     // [192]
#define OFF_C1   3348     // [78][32] bf16 -> 78*16 u32 = 1248
#define OFF_AB   4596     // [32 samples][388 u32]; rows: A0..A11,B0..B11, 16 u32 each
#define AB_STRIDE 388
#define SMEM_U32 (OFF_AB + SPB * AB_STRIDE)   // 17012 u32 = 68048 B

extern __shared__ float smem[];

__device__ __forceinline__ float2 bf2f(unsigned u) {
    __nv_bfloat162 h = *reinterpret_cast<__nv_bfloat162*>(&u);
    return __bfloat1622float2(h);
}
__device__ __forceinline__ unsigned f2bf(float a, float b) {
    __nv_bfloat162 h = __floats2bfloat162_rn(a, b);
    return *reinterpret_cast<unsigned*>(&h);
}

__global__ void __launch_bounds__(THREADS, 2)
pin_kernel(const float* __restrict__ x_cont, const int* __restrict__ x_cat,
           const float* __restrict__ exposure,
           const float* __restrict__ cont_W1, const float* __restrict__ cont_b1,
           const float* __restrict__ cont_W2, const float* __restrict__ cont_b2,
           const float* __restrict__ cat_tables, const float* __restrict__ tokens,
           const float* __restrict__ sW1, const float* __restrict__ sb1,
           const float* __restrict__ sW2, const float* __restrict__ sb2,
           const float* __restrict__ sW3, const float* __restrict__ sb3,
           const float* __restrict__ out_w, const float* __restrict__ out_b,
           float* __restrict__ out)
{
    unsigned* smemu = (unsigned*)smem;
    const int tid  = threadIdx.x;
    const int lane = tid & 31;   // sample within block
    const int sub  = tid >> 5;   // 0..5

    // ---------------- staging ----------------
    for (int i = tid; i < 320; i += THREADS) {
        int d = i >> 5, l = i & 31;
        smem[OFF_WA + i] = (l < 30) ? sW1[d * 30 + l] : 0.f;
        smem[OFF_WB + i] = (l < 30) ? sW1[(10 + d) * 30 + l] : 0.f;
    }
    for (int i = tid; i < 640; i += THREADS) {      // W2 rows, zero-padded
        int l = i / 20, o = i % 20;
        smem[OFF_W2 + i] = (l < 30) ? sW2[l * 20 + o] : 0.f;
    }
    for (int i = tid; i < 20; i += THREADS) {
        smem[OFF_W3 + i]  = sW3[i];
        smem[OFF_SB2 + i] = sb2[i];
    }
    for (int i = tid; i < 120; i += THREADS) {
        smem[OFF_CW1 + i] = cont_W1[i];
        smem[OFF_CB1 + i] = cont_b1[i];
    }
    for (int i = tid; i < 1200; i += THREADS) {
        int c = i / 200, r = i % 200, h = r / 10, d = r % 10;
        smem[OFF_CW2 + (c * 20 + h) * 12 + d] = cont_W2[i];
    }
    for (int i = tid; i < 60; i += THREADS)
        smem[OFF_CB2 + (i / 10) * 12 + (i % 10)] = cont_b2[i];
    for (int i = tid; i < 78; i += THREADS) smem[OFF_OUTW + i] = out_w[i];
    if (tid == 0) { smem[OFF_MISC + 0] = sb3[0]; smem[OFF_MISC + 1] = out_b[0]; }
    // C1 as bf16 pairs: c1[p][l] = sb1[l] + tok_p . sW1[20:30, l]
    for (int i = tid; i < 78 * 16; i += THREADS) {
        int p = i >> 4, lp = i & 15;
        int l0 = lp * 2, l1 = l0 + 1;
        float v0 = 0.f, v1 = 0.f;
        if (l0 < 30) {
            v0 = sb1[l0];
#pragma unroll
            for (int d = 0; d < 10; ++d)
                v0 = fmaf(tokens[p * 10 + d], sW1[(20 + d) * 30 + l0], v0);
        }
        if (l1 < 30) {
            v1 = sb1[l1];
#pragma unroll
            for (int d = 0; d < 10; ++d)
                v1 = fmaf(tokens[p * 10 + d], sW1[(20 + d) * 30 + l1], v1);
        }
        smemu[OFF_C1 + i] = f2bf(v0, v1);
    }
    __syncthreads();

    // ---------------- per-sample feature + projection phase ----------------
    const int b = blockIdx.x * SPB + lane;
    unsigned* myAB = smemu + OFF_AB + lane * AB_STRIDE;

    float e[10];
    // continuous feature c = sub
    {
        int c = sub;
        float x = x_cont[b * 6 + c];
#pragma unroll
        for (int d = 0; d < 10; ++d) e[d] = smem[OFF_CB2 + c * 12 + d];
#pragma unroll
        for (int h = 0; h < 20; ++h) {
            float hv = fmaxf(fmaf(x, smem[OFF_CW1 + c * 20 + h],
                                  smem[OFF_CB1 + c * 20 + h]), 0.f);
#pragma unroll
            for (int d = 0; d < 10; ++d)
                e[d] = fmaf(hv, smem[OFF_CW2 + (c * 20 + h) * 12 + d], e[d]);
        }
    }
    // project feature q into A row q and B row 12+q (bf16)
#pragma unroll 1
    for (int proj = 0; proj < 2; ++proj) {
        const float* W = smem + (proj ? OFF_WB : OFF_WA);
        float acc[32];
#pragma unroll
        for (int l = 0; l < 32; ++l) acc[l] = 0.f;
#pragma unroll
        for (int d = 0; d < 10; ++d) {
#pragma unroll
            for (int l = 0; l < 32; ++l)
                acc[l] = fmaf(e[d], W[d * 32 + l], acc[l]);
        }
        unsigned* dst = myAB + (proj ? (12 + sub) : sub) * 16;
#pragma unroll
        for (int i = 0; i < 16; ++i) dst[i] = f2bf(acc[2 * i], acc[2 * i + 1]);
    }
    // categorical feature c = sub -> rows 6+sub / 18+sub
    {
        int c = sub;
        int idx = x_cat[b * 6 + c];
        const float2* row = (const float2*)(cat_tables + (size_t)(c * 100 + idx) * 10);
#pragma unroll
        for (int d = 0; d < 5; ++d) { float2 v = row[d]; e[2*d] = v.x; e[2*d+1] = v.y; }
    }
#pragma unroll 1
    for (int proj = 0; proj < 2; ++proj) {
        const float* W = smem + (proj ? OFF_WB : OFF_WA);
        float acc[32];
#pragma unroll
        for (int l = 0; l < 32; ++l) acc[l] = 0.f;
#pragma unroll
        for (int d = 0; d < 10; ++d) {
#pragma unroll
            for (int l = 0; l < 32; ++l)
                acc[l] = fmaf(e[d], W[d * 32 + l], acc[l]);
        }
        unsigned* dst = myAB + (proj ? (18 + sub) : (6 + sub)) * 16;
#pragma unroll
        for (int i = 0; i < 16; ++i) dst[i] = f2bf(acc[2 * i], acc[2 * i + 1]);
    }
    __syncthreads();

    // ---------------- pair loop: rows {sub, 11-sub} = 13 pairs ----------------
    const float raw_bias = smem[OFF_MISC + 0];
    float eta = 0.f;

#pragma unroll 1
    for (int r = 0; r < 2; ++r) {
        const int j = r ? (11 - sub) : sub;
        const int pbase = (j * (25 - j)) >> 1;
        const uint4* Aj = (const uint4*)(myAB + j * 16);

#pragma unroll 1
        for (int k = j; k < 12; ++k) {
            const int p = pbase + (k - j);
            const uint4* Bk = (const uint4*)(myAB + (12 + k) * 16);
            const uint4* Cp = (const uint4*)(smemu + OFF_C1 + p * 16);

            float h2[20];
            {
                const float4* sb = (const float4*)(smem + OFF_SB2);
#pragma unroll
                for (int v = 0; v < 5; ++v) {
                    float4 s = sb[v];
                    h2[v*4+0]=s.x; h2[v*4+1]=s.y; h2[v*4+2]=s.z; h2[v*4+3]=s.w;
                }
            }

#pragma unroll 1
            for (int g = 0; g < 4; ++g) {
                uint4 ag = Aj[g], bg = Bk[g], cg = Cp[g];
                float2 a0 = bf2f(ag.x), a1 = bf2f(ag.y), a2 = bf2f(ag.z), a3 = bf2f(ag.w);
                float2 b0 = bf2f(bg.x), b1 = bf2f(bg.y), b2 = bf2f(bg.z), b3 = bf2f(bg.w);
                float2 c0 = bf2f(cg.x), c1v = bf2f(cg.y), c2 = bf2f(cg.z), c3 = bf2f(cg.w);
                float h1[8];
                h1[0] = fmaxf(a0.x + b0.x + c0.x, 0.f);
                h1[1] = fmaxf(a0.y + b0.y + c0.y, 0.f);
                h1[2] = fmaxf(a1.x + b1.x + c1v.x, 0.f);
                h1[3] = fmaxf(a1.y + b1.y + c1v.y, 0.f);
                h1[4] = fmaxf(a2.x + b2.x + c2.x, 0.f);
                h1[5] = fmaxf(a2.y + b2.y + c2.y, 0.f);
                h1[6] = fmaxf(a3.x + b3.x + c3.x, 0.f);
                h1[7] = fmaxf(a3.y + b3.y + c3.y, 0.f);

                const float* w2b = smem + OFF_W2 + g * 160;   // 8 rows x 20
#pragma unroll 2
                for (int i = 0; i < 8; ++i) {
                    const float4* wr = (const float4*)(w2b + i * 20);
                    float4 w0 = wr[0], w1 = wr[1], w2v = wr[2], w3v = wr[3], w4 = wr[4];
                    float h = h1[i];
                    h2[0]  = fmaf(h, w0.x, h2[0]);  h2[1]  = fmaf(h, w0.y, h2[1]);
                    h2[2]  = fmaf(h, w0.z, h2[2]);  h2[3]  = fmaf(h, w0.w, h2[3]);
                    h2[4]  = fmaf(h, w1.x, h2[4]);  h2[5]  = fmaf(h, w1.y, h2[5]);
                    h2[6]  = fmaf(h, w1.z, h2[6]);  h2[7]  = fmaf(h, w1.w, h2[7]);
                    h2[8]  = fmaf(h, w2v.x, h2[8]); h2[9]  = fmaf(h, w2v.y, h2[9]);
                    h2[10] = fmaf(h, w2v.z, h2[10]);h2[11] = fmaf(h, w2v.w, h2[11]);
                    h2[12] = fmaf(h, w3v.x, h2[12]);h2[13] = fmaf(h, w3v.y, h2[13]);
                    h2[14] = fmaf(h, w3v.z, h2[14]);h2[15] = fmaf(h, w3v.w, h2[15]);
                    h2[16] = fmaf(h, w4.x, h2[16]); h2[17] = fmaf(h, w4.y, h2[17]);
                    h2[18] = fmaf(h, w4.z, h2[18]); h2[19] = fmaf(h, w4.w, h2[19]);
                }
            }

            float raw = raw_bias;
            {
                const float4* w3r = (const float4*)(smem + OFF_W3);
#pragma unroll
                for (int v = 0; v < 5; ++v) {
                    float4 w = w3r[v];
                    raw = fmaf(fmaxf(h2[v*4+0], 0.f), w.x, raw);
                    raw = fmaf(fmaxf(h2[v*4+1], 0.f), w.y, raw);
                    raw = fmaf(fmaxf(h2[v*4+2], 0.f), w.z, raw);
                    raw = fmaf(fmaxf(h2[v*4+3], 0.f), w.w, raw);
                }
            }
            float ht = fminf(fmaxf(raw * (1.f/6.f) + 0.5f, 0.f), 1.f) - 0.5f;
            eta = fmaf(smem[OFF_OUTW + p], ht, eta);
        }
    }

    smem[OFF_PETA + tid] = eta;
    __syncthreads();
    if (tid < 32) {
        float esum = 0.f;
#pragma unroll
        for (int s = 0; s < 6; ++s) esum += smem[OFF_PETA + tid + 32 * s];
        esum += smem[OFF_MISC + 1];
        esum = fminf(fmaxf(esum, -20.f), 20.f);
        out[b] = __expf(esum) * exposure[b];
    }
}

extern "C" void kernel_launch(void* const* d_in, const int* in_sizes, int n_in,
                              void* d_out, int out_size)
{
    (void)in_sizes; (void)n_in; (void)out_size;
    size_t shmem = SMEM_U32 * 4;
    cudaFuncSetAttribute(pin_kernel, cudaFuncAttributeMaxDynamicSharedMemorySize,
                         (int)shmem);
    pin_kernel<<<NB / SPB, THREADS, shmem>>>(
        (const float*)d_in[0],  (const int*)d_in[1],   (const float*)d_in[2],
        (const float*)d_in[3],  (const float*)d_in[4], (const float*)d_in[5],
        (const float*)d_in[6],  (const float*)d_in[7], (const float*)d_in[8],
        (const float*)d_in[9],  (const float*)d_in[10],(const float*)d_in[11],
        (const float*)d_in[12], (const float*)d_in[13],(const float*)d_in[14],
        (const float*)d_in[15], (const float*)d_in[16],
        (float*)d_out);
}